// round 6
// baseline (speedup 1.0000x reference)
#include <cuda_runtime.h>

#define Hn   512
#define Tn   128
#define Bn   64
#define NROW 128
#define G4   2048
#define KE   1024
#define NTOK 8192

typedef unsigned long long ull;

// ---------------- static device scratch ----------------
__device__ __align__(16) float g_temb[(size_t)NTOK * KE];      // [tok][1024]
__device__ __align__(16) float g_WtT [(size_t)KE * G4];        // [j][p] p interleaved u*4+g
__device__ __align__(16) float g_Whh2[(size_t)Hn * G4];        // [jp][unit*8 + g*2 + par]
__device__ __align__(16) float g_G   [(size_t)Tn * NROW * G4]; // [t'][r][p]
__device__ __align__(16) float g_Msp [2][8][G4];
__device__ __align__(16) float g_cst [2][G4];
__device__ __align__(16) float g_h   [2][NROW * Hn];
__device__ __align__(16) float g_c   [NROW * Hn];
__device__ __align__(16) float g_hfin[NROW * Hn];

// ---------------- helpers ----------------
__device__ __forceinline__ void fma2(ull& d, ull a, ull b) {
    asm("fma.rn.f32x2 %0, %1, %2, %0;" : "+l"(d) : "l"(a), "l"(b));
}
__device__ __forceinline__ float sum2(ull v) {
    float a, b;
    asm("mov.b64 {%0,%1}, %2;" : "=f"(a), "=f"(b) : "l"(v));
    return a + b;
}
__device__ __forceinline__ float sigf(float v) { return 1.0f / (1.0f + __expf(-v)); }

// ---------------- prep: fold segment linears through W_ih ----------------
__global__ void k_fold(const float* __restrict__ Wih,
                       const float* __restrict__ Wis0, const float* __restrict__ bis0,
                       const float* __restrict__ Wis1, const float* __restrict__ bis1,
                       const float* __restrict__ bih,  const float* __restrict__ bhh) {
    int idx = blockIdx.x * blockDim.x + threadIdx.x;   // 32768 = 2048 p * 16 items
    int p = idx >> 4, item = idx & 15;
    int u = p >> 2, g = p & 3;
    const float* wr = Wih + (size_t)(g * Hn + u) * 1536;
    float acc = 0.0f;
    if (item < 8) {
        for (int k = 0; k < Hn; k++) acc += wr[k] * Wis0[k * 8 + item];
        g_Msp[0][item][p] = acc;
    } else if (item < 14) {
        int m = item - 8;
        for (int k = 0; k < Hn; k++) acc += wr[k] * Wis1[k * 6 + m];
        g_Msp[1][m][p] = acc;
    } else if (item == 14) {
        for (int k = 0; k < Hn; k++) acc += wr[k] * bis0[k];
        g_cst[0][p] = acc + bih[g * Hn + u] + bhh[g * Hn + u];
    } else {
        for (int k = 0; k < Hn; k++) acc += wr[k] * bis1[k];
        g_cst[1][p] = acc + bih[g * Hn + u] + bhh[g * Hn + u];
    }
}

// ---------------- prep: permuted weight copies ----------------
__global__ void k_wtT(const float* __restrict__ Wih) {
    int i = blockIdx.x * blockDim.x + threadIdx.x;     // KE*G4 = 2097152 exact
    int j = i >> 11, p = i & 2047;
    int u = p >> 2, g = p & 3;
    g_WtT[i] = Wih[(size_t)(g * Hn + u) * 1536 + 512 + j];
}

__global__ void k_whh2(const float* __restrict__ Whh) {
    int i = blockIdx.x * blockDim.x + threadIdx.x;     // Hn*G4 = 1048576 exact
    int jp = i >> 12, rem = i & 4095;
    int u = rem >> 3, g = (rem >> 1) & 3, par = i & 1;
    g_Whh2[i] = Whh[(size_t)(g * Hn + u) * Hn + 2 * jp + par];
}

__global__ void k_init(const float* __restrict__ h0, const float* __restrict__ c0) {
    int i = blockIdx.x * blockDim.x + threadIdx.x;     // 65536 exact
    int r = i >> 9, u = i & 511;
    g_h[0][i] = h0[(r >> 1) * Hn + u];
    g_c[i]    = c0[(r >> 1) * Hn + u];
}

// ---------------- timestep embeddings ----------------
__global__ void k_temb(const float* __restrict__ x) {
    int tok = blockIdx.x;
    int k   = threadIdx.x;   // 256
    float t0 = x[tok * 16 + 0], t1 = x[tok * 16 + 1];
    float fr = expf(-9.210340371976184f * (float)k * (1.0f / 256.0f));
    float s0, c0v, s1, c1v;
    sincosf(t0 * fr, &s0, &c0v);
    sincosf(t1 * fr, &s1, &c1v);
    float* o = g_temb + (size_t)tok * KE;
    o[k]       = c0v;
    o[k + 256] = s0;
    o[k + 512] = c1v;
    o[k + 768] = s1;
}

// ---------------- big GEMM: temb -> gate pre-activations (+ seg fold epilogue) ----------------
// C[tok][p] = temb[tok][:] . WtT[:, p]; tile BM=128(t of one b) x BN=64(p), BK=32.
__global__ void __launch_bounds__(256) k_gemm(const float* __restrict__ x) {
    __shared__ float As[16 * 128 * 2];   // [kp][m][par]
    __shared__ float Bs[16 * 64 * 2];    // [kp][n][par]
    int b  = blockIdx.y;
    int pt = blockIdx.x * 64;
    int tid = threadIdx.x;
    int tx = tid & 15, ty = tid >> 4;
    int m0 = ty * 8, n0 = tx * 4;

    ull acc[8][4];
    #pragma unroll
    for (int i = 0; i < 8; i++)
        #pragma unroll
        for (int j = 0; j < 4; j++) acc[i][j] = 0ull;

    const float* Abase = g_temb + (size_t)b * 128 * KE;

    for (int k0 = 0; k0 < KE; k0 += 32) {
        #pragma unroll
        for (int it = 0; it < 4; it++) {
            int m  = (tid >> 3) + it * 32;
            int kk = (tid & 7) * 4;
            float4 v = *(const float4*)(Abase + (size_t)m * KE + k0 + kk);
            int kp = kk >> 1;
            As[(kp * 128 + m) * 2 + 0]       = v.x;
            As[(kp * 128 + m) * 2 + 1]       = v.y;
            As[((kp + 1) * 128 + m) * 2 + 0] = v.z;
            As[((kp + 1) * 128 + m) * 2 + 1] = v.w;
        }
        #pragma unroll
        for (int it = 0; it < 2; it++) {
            int j  = (tid >> 4) + it * 16;
            int pp = (tid & 15) * 4;
            float4 v = *(const float4*)(g_WtT + (size_t)(k0 + j) * G4 + pt + pp);
            int kp = j >> 1, par = j & 1;
            Bs[(kp * 64 + pp + 0) * 2 + par] = v.x;
            Bs[(kp * 64 + pp + 1) * 2 + par] = v.y;
            Bs[(kp * 64 + pp + 2) * 2 + par] = v.z;
            Bs[(kp * 64 + pp + 3) * 2 + par] = v.w;
        }
        __syncthreads();
        #pragma unroll
        for (int kp = 0; kp < 16; kp++) {
            ull a2[8], b2[4];
            #pragma unroll
            for (int i = 0; i < 8; i += 2) {
                ulonglong2 t = *(const ulonglong2*)&As[(kp * 128 + m0 + i) * 2];
                a2[i] = t.x; a2[i + 1] = t.y;
            }
            #pragma unroll
            for (int i = 0; i < 4; i += 2) {
                ulonglong2 t = *(const ulonglong2*)&Bs[(kp * 64 + n0 + i) * 2];
                b2[i] = t.x; b2[i + 1] = t.y;
            }
            #pragma unroll
            for (int i = 0; i < 8; i++)
                #pragma unroll
                for (int j = 0; j < 4; j++) fma2(acc[i][j], a2[i], b2[j]);
        }
        __syncthreads();
    }

    // epilogue: add folded segment contribution, route to G[t'][r][p] per the concat/reshape quirk
    #pragma unroll
    for (int i = 0; i < 8; i++) {
        int t = m0 + i;
        const float* xr = x + ((size_t)b * 128 + t) * 16;
        float cval[4];
        #pragma unroll
        for (int j = 0; j < 4; j++) cval[j] = sum2(acc[i][j]);
        #pragma unroll
        for (int se = 0; se < 2; se++) {
            float4 outv;
            float* ov = &outv.x;
            int p = pt + n0;
            #pragma unroll
            for (int j = 0; j < 4; j++) {
                float v = cval[j] + g_cst[se][p + j];
                if (se == 0) {
                    #pragma unroll
                    for (int m = 0; m < 8; m++) v += xr[2 + m] * g_Msp[0][m][p + j];
                } else {
                    #pragma unroll
                    for (int m = 0; m < 6; m++) v += xr[10 + m] * g_Msp[1][m][p + j];
                }
                ov[j] = v;
            }
            int L = t * 2 + se;
            int sp = L >> 7, tp = L & 127;   // scan segment, scan step
            *(float4*)&g_G[((size_t)tp * NROW + (b * 2 + sp)) * G4 + p] = outv;
        }
    }
}

// ---------------- one recurrence step: gates = G + h.Whh^T, LSTM update ----------------
// grid (16 p-tiles, 8 row-tiles), 128 threads. thread = 4 rows x 1 unit (4 gates).
__global__ void __launch_bounds__(128) k_step(int t, const int* __restrict__ lengths) {
    __shared__ float hs[256 * 36];   // [jp][row*2+par], padded stride 36
    int tid  = threadIdx.x;
    int warp = tid >> 5, lane = tid & 31;
    int ul = lane >> 2, rslot = lane & 3;
    int unit    = blockIdx.x * 32 + warp * 8 + ul;
    int rowbase = blockIdx.y * 16;

    const float* hin  = g_h[t & 1];
    float*       hout = g_h[(t + 1) & 1];

    for (int e = tid; e < 16 * 512; e += 128) {
        int rl = e >> 9, j = e & 511;
        hs[(j >> 1) * 36 + rl * 2 + (j & 1)] = hin[(rowbase + rl) * Hn + j];
    }
    __syncthreads();

    ull acc[4][4];
    #pragma unroll
    for (int i = 0; i < 4; i++)
        #pragma unroll
        for (int g = 0; g < 4; g++) acc[i][g] = 0ull;

    const float* wptr = g_Whh2 + unit * 8;
    const float* hp   = hs + rslot * 8;
    #pragma unroll 4
    for (int jp = 0; jp < 256; jp++) {
        ulonglong2 wA  = *(const ulonglong2*)(wptr + (size_t)jp * 4096);
        ulonglong2 wB  = *(const ulonglong2*)(wptr + (size_t)jp * 4096 + 4);
        ulonglong2 h01 = *(const ulonglong2*)(hp + jp * 36);
        ulonglong2 h23 = *(const ulonglong2*)(hp + jp * 36 + 4);
        fma2(acc[0][0], h01.x, wA.x); fma2(acc[0][1], h01.x, wA.y);
        fma2(acc[0][2], h01.x, wB.x); fma2(acc[0][3], h01.x, wB.y);
        fma2(acc[1][0], h01.y, wA.x); fma2(acc[1][1], h01.y, wA.y);
        fma2(acc[1][2], h01.y, wB.x); fma2(acc[1][3], h01.y, wB.y);
        fma2(acc[2][0], h23.x, wA.x); fma2(acc[2][1], h23.x, wA.y);
        fma2(acc[2][2], h23.x, wB.x); fma2(acc[2][3], h23.x, wB.y);
        fma2(acc[3][0], h23.y, wA.x); fma2(acc[3][1], h23.y, wA.y);
        fma2(acc[3][2], h23.y, wB.x); fma2(acc[3][3], h23.y, wB.y);
    }

    #pragma unroll
    for (int i = 0; i < 4; i++) {
        int r = rowbase + rslot * 4 + i;
        float4 gin = *(const float4*)&g_G[((size_t)t * NROW + r) * G4 + unit * 4];
        float iv = sum2(acc[i][0]) + gin.x;
        float fv = sum2(acc[i][1]) + gin.y;
        float gv = sum2(acc[i][2]) + gin.z;
        float ov = sum2(acc[i][3]) + gin.w;
        float ig = sigf(iv), fg = sigf(fv), og = sigf(ov);
        float gg = tanhf(gv);
        float c = fg * g_c[r * Hn + unit] + ig * gg;
        g_c[r * Hn + unit] = c;
        float h = og * tanhf(c);
        hout[r * Hn + unit] = h;
        if (t + 1 == lengths[r >> 1]) g_hfin[r * Hn + unit] = h;
    }
}

// ---------------- output head ----------------
__global__ void k_out(const float* __restrict__ Wo, const float* __restrict__ bo,
                      float* __restrict__ out) {
    __shared__ float red[14][129];
    int b = blockIdx.x, tid = threadIdx.x;   // 128 threads
    float acc[14];
    #pragma unroll
    for (int o = 0; o < 14; o++) acc[o] = 0.0f;
    for (int q = tid; q < 1024; q += 128) {
        float hv = g_hfin[b * 1024 + q];
        #pragma unroll
        for (int o = 0; o < 14; o++) acc[o] += hv * Wo[o * 1024 + q];
    }
    #pragma unroll
    for (int o = 0; o < 14; o++) red[o][tid] = acc[o];
    __syncthreads();
    if (tid < 14) {
        float s = bo[tid];
        for (int k = 0; k < 128; k++) s += red[tid][k];
        out[b * 14 + tid] = sigf(s);
    }
}

// ---------------- launch ----------------
extern "C" void kernel_launch(void* const* d_in, const int* in_sizes, int n_in,
                              void* d_out, int out_size) {
    const float* x    = (const float*)d_in[0];
    const int*   len  = (const int*)  d_in[1];
    const float* h0   = (const float*)d_in[2];
    const float* c0   = (const float*)d_in[3];
    const float* Wis0 = (const float*)d_in[4];
    const float* bis0 = (const float*)d_in[5];
    const float* Wis1 = (const float*)d_in[6];
    const float* bis1 = (const float*)d_in[7];
    const float* Wih  = (const float*)d_in[8];
    const float* Whh  = (const float*)d_in[9];
    const float* bih  = (const float*)d_in[10];
    const float* bhh  = (const float*)d_in[11];
    const float* Wo   = (const float*)d_in[12];
    const float* bo   = (const float*)d_in[13];
    float* out = (float*)d_out;

    k_fold<<<128, 256>>>(Wih, Wis0, bis0, Wis1, bis1, bih, bhh);
    k_wtT <<<8192, 256>>>(Wih);
    k_whh2<<<4096, 256>>>(Whh);
    k_init<<<256, 256>>>(h0, c0);
    k_temb<<<8192, 256>>>(x);
    k_gemm<<<dim3(32, 64), 256>>>(x);
    for (int t = 0; t < 128; t++)
        k_step<<<dim3(16, 8), 128>>>(t, len);
    k_out<<<64, 128>>>(Wo, bo, out);
}

// round 9
// speedup vs baseline: 1.5038x; 1.5038x over previous
#include <cuda_runtime.h>

#define Hn   512
#define Tn   128
#define Bn   64
#define NROW 128
#define G4   2048
#define KE   1024
#define NTOK 8192

typedef unsigned long long ull;

// ---------------- static device scratch ----------------
__device__ __align__(16) float g_temb[(size_t)NTOK * KE];      // [tok][1024]
__device__ __align__(16) float g_WtT [(size_t)KE * G4];        // [j][p] p interleaved u*4+g
__device__ __align__(16) float g_Whh2[(size_t)Hn * G4];        // [jp][u*8 + g*2 + par], 256 jp x 4096
__device__ __align__(16) float g_G   [(size_t)Tn * NROW * G4]; // [t'][r][p]
__device__ __align__(16) float g_Msp [2][8][G4];
__device__ __align__(16) float g_cst [2][G4];
__device__ __align__(16) float g_h   [2][NROW * Hn];
__device__ __align__(16) float g_hfin[NROW * Hn];
__device__ int          g_ctr;
__device__ volatile int g_rel;

// ---------------- helpers ----------------
__device__ __forceinline__ void fma2(ull& d, ull a, ull b) {
    asm("fma.rn.f32x2 %0, %1, %2, %0;" : "+l"(d) : "l"(a), "l"(b));
}
__device__ __forceinline__ float sum2(ull v) {
    float a, b;
    asm("mov.b64 {%0,%1}, %2;" : "=f"(a), "=f"(b) : "l"(v));
    return a + b;
}
__device__ __forceinline__ float sigf(float v) { return 1.0f / (1.0f + __expf(-v)); }

// ---------------- prep: fold segment linears through W_ih ----------------
__global__ void k_fold(const float* __restrict__ Wih,
                       const float* __restrict__ Wis0, const float* __restrict__ bis0,
                       const float* __restrict__ Wis1, const float* __restrict__ bis1,
                       const float* __restrict__ bih,  const float* __restrict__ bhh) {
    int idx = blockIdx.x * blockDim.x + threadIdx.x;   // 32768 = 2048 p * 16 items
    int p = idx >> 4, item = idx & 15;
    int u = p >> 2, g = p & 3;
    const float* wr = Wih + (size_t)(g * Hn + u) * 1536;
    float acc = 0.0f;
    if (item < 8) {
        for (int k = 0; k < Hn; k++) acc += wr[k] * Wis0[k * 8 + item];
        g_Msp[0][item][p] = acc;
    } else if (item < 14) {
        int m = item - 8;
        for (int k = 0; k < Hn; k++) acc += wr[k] * Wis1[k * 6 + m];
        g_Msp[1][m][p] = acc;
    } else if (item == 14) {
        for (int k = 0; k < Hn; k++) acc += wr[k] * bis0[k];
        g_cst[0][p] = acc + bih[g * Hn + u] + bhh[g * Hn + u];
    } else {
        for (int k = 0; k < Hn; k++) acc += wr[k] * bis1[k];
        g_cst[1][p] = acc + bih[g * Hn + u] + bhh[g * Hn + u];
    }
}

// ---------------- prep: permuted weight copies ----------------
__global__ void k_wtT(const float* __restrict__ Wih) {
    int i = blockIdx.x * blockDim.x + threadIdx.x;     // KE*G4 = 2097152 exact
    int j = i >> 11, p = i & 2047;
    int u = p >> 2, g = p & 3;
    g_WtT[i] = Wih[(size_t)(g * Hn + u) * 1536 + 512 + j];
}

__global__ void k_whh2(const float* __restrict__ Whh) {
    int i = blockIdx.x * blockDim.x + threadIdx.x;     // Hn*G4 = 1048576 exact
    int jp = i >> 12, rem = i & 4095;
    int u = rem >> 3, g = (rem >> 1) & 3, par = i & 1;
    g_Whh2[i] = Whh[(size_t)(g * Hn + u) * Hn + 2 * jp + par];
}

__global__ void k_inith(const float* __restrict__ h0) {
    int i = blockIdx.x * blockDim.x + threadIdx.x;     // 65536 exact
    int r = i >> 9, u = i & 511;
    g_h[0][i] = h0[(r >> 1) * Hn + u];
    if (i == 0) { g_ctr = 0; g_rel = 0; }
}

// ---------------- timestep embeddings ----------------
__global__ void k_temb(const float* __restrict__ x) {
    int tok = blockIdx.x;
    int k   = threadIdx.x;   // 256
    float t0 = x[tok * 16 + 0], t1 = x[tok * 16 + 1];
    float fr = __expf(-9.210340371976184f * (float)k * (1.0f / 256.0f));
    float s0, c0v, s1, c1v;
    __sincosf(t0 * fr, &s0, &c0v);
    __sincosf(t1 * fr, &s1, &c1v);
    float* o = g_temb + (size_t)tok * KE;
    o[k]       = c0v;
    o[k + 256] = s0;
    o[k + 512] = c1v;
    o[k + 768] = s1;
}

// ---------------- big GEMM: temb -> gate pre-activations (+ seg fold epilogue) ----------------
__global__ void __launch_bounds__(256) k_gemm(const float* __restrict__ x) {
    __shared__ float As[16 * 128 * 2];   // [kp][m][par]
    __shared__ float Bs[16 * 64 * 2];    // [kp][n][par]
    int b  = blockIdx.y;
    int pt = blockIdx.x * 64;
    int tid = threadIdx.x;
    int tx = tid & 15, ty = tid >> 4;
    int m0 = ty * 8, n0 = tx * 4;

    ull acc[8][4];
    #pragma unroll
    for (int i = 0; i < 8; i++)
        #pragma unroll
        for (int j = 0; j < 4; j++) acc[i][j] = 0ull;

    const float* Abase = g_temb + (size_t)b * 128 * KE;

    for (int k0 = 0; k0 < KE; k0 += 32) {
        #pragma unroll
        for (int it = 0; it < 4; it++) {
            int m  = (tid >> 3) + it * 32;
            int kk = (tid & 7) * 4;
            float4 v = *(const float4*)(Abase + (size_t)m * KE + k0 + kk);
            int kp = kk >> 1;
            As[(kp * 128 + m) * 2 + 0]       = v.x;
            As[(kp * 128 + m) * 2 + 1]       = v.y;
            As[((kp + 1) * 128 + m) * 2 + 0] = v.z;
            As[((kp + 1) * 128 + m) * 2 + 1] = v.w;
        }
        #pragma unroll
        for (int it = 0; it < 2; it++) {
            int j  = (tid >> 4) + it * 16;
            int pp = (tid & 15) * 4;
            float4 v = *(const float4*)(g_WtT + (size_t)(k0 + j) * G4 + pt + pp);
            int kp = j >> 1, par = j & 1;
            Bs[(kp * 64 + pp + 0) * 2 + par] = v.x;
            Bs[(kp * 64 + pp + 1) * 2 + par] = v.y;
            Bs[(kp * 64 + pp + 2) * 2 + par] = v.z;
            Bs[(kp * 64 + pp + 3) * 2 + par] = v.w;
        }
        __syncthreads();
        #pragma unroll
        for (int kp = 0; kp < 16; kp++) {
            ull a2[8], b2[4];
            #pragma unroll
            for (int i = 0; i < 8; i += 2) {
                ulonglong2 t = *(const ulonglong2*)&As[(kp * 128 + m0 + i) * 2];
                a2[i] = t.x; a2[i + 1] = t.y;
            }
            #pragma unroll
            for (int i = 0; i < 4; i += 2) {
                ulonglong2 t = *(const ulonglong2*)&Bs[(kp * 64 + n0 + i) * 2];
                b2[i] = t.x; b2[i + 1] = t.y;
            }
            #pragma unroll
            for (int i = 0; i < 8; i++)
                #pragma unroll
                for (int j = 0; j < 4; j++) fma2(acc[i][j], a2[i], b2[j]);
        }
        __syncthreads();
    }

    #pragma unroll
    for (int i = 0; i < 8; i++) {
        int t = m0 + i;
        const float* xr = x + ((size_t)b * 128 + t) * 16;
        float cval[4];
        #pragma unroll
        for (int j = 0; j < 4; j++) cval[j] = sum2(acc[i][j]);
        #pragma unroll
        for (int se = 0; se < 2; se++) {
            float4 outv;
            float* ov = &outv.x;
            int p = pt + n0;
            #pragma unroll
            for (int j = 0; j < 4; j++) {
                float v = cval[j] + g_cst[se][p + j];
                if (se == 0) {
                    #pragma unroll
                    for (int m = 0; m < 8; m++) v += xr[2 + m] * g_Msp[0][m][p + j];
                } else {
                    #pragma unroll
                    for (int m = 0; m < 6; m++) v += xr[10 + m] * g_Msp[1][m][p + j];
                }
                ov[j] = v;
            }
            int L = t * 2 + se;
            int sp = L >> 7, tp = L & 127;
            *(float4*)&g_G[((size_t)tp * NROW + (b * 2 + sp)) * G4 + p] = outv;
        }
    }
}

// ---------------- persistent recurrence kernel ----------------
// grid (32 unit-tiles, 4 row-tiles) = 128 co-resident blocks, 256 threads.
// block = 32 rows x 16 units; thread = 4 rows x 1 unit x half-K.
// Per-block W_hh slice = 128KB -> L1-resident across all 128 steps.
// c and final-h capture live in registers. Split-K halves the serial fma2 chain;
// an 8KB smem reduction recombines the two K-halves.
#define HS_STRIDE 516
#define RED_OFF   (32 * HS_STRIDE)
#define RNN_SMEM  ((RED_OFF + 128 * 16) * 4)

__global__ void __launch_bounds__(256, 1) k_rnn(const int* __restrict__ lengths,
                                                const float* __restrict__ c0) {
    extern __shared__ float hs[];            // [32 rows][516] + red[128][16]
    float* red = hs + RED_OFF;
    int tid    = threadIdx.x;
    int uidx   = tid & 15;
    int rslot  = (tid >> 4) & 7;             // 0..7
    int jhalf  = tid >> 7;                   // 0/1
    int unit   = blockIdx.x * 16 + uidx;
    int rowbase = blockIdx.y * 32;
    int r0 = rowbase + rslot * 4;
    int jp0 = jhalf * 128;

    float c[4];
    int   mylen[4];
    #pragma unroll
    for (int i = 0; i < 4; i++) {
        c[i]     = __ldg(&c0[((r0 + i) >> 1) * Hn + unit]);
        mylen[i] = __ldg(&lengths[(r0 + i) >> 1]);
    }

    const float* wbase = g_Whh2 + unit * 8;

    for (int t = 0; t < 128; t++) {
        const float* hin  = g_h[t & 1];
        float*       hout = g_h[(t + 1) & 1];

        // stage full 32-row h tile (32 x 512 = 4096 float4s); bypass L1
        #pragma unroll
        for (int e = tid; e < 4096; e += 256) {
            int rl = e >> 7, u4 = (e & 127) << 2;
            float4 v = __ldcg((const float4*)(hin + (size_t)(rowbase + rl) * Hn + u4));
            *(float4*)&hs[rl * HS_STRIDE + u4] = v;
        }
        __syncthreads();

        // prefetch this step's gate pre-activations early (epilogue threads only)
        float4 gin[4];
        if (jhalf == 0) {
            #pragma unroll
            for (int i = 0; i < 4; i++)
                gin[i] = __ldcg((const float4*)(g_G + ((size_t)t * NROW + r0 + i) * G4 + unit * 4));
        }

        ull acc[4][4];
        #pragma unroll
        for (int i = 0; i < 4; i++)
            #pragma unroll
            for (int g = 0; g < 4; g++) acc[i][g] = 0ull;

        const float* hp = hs + (size_t)(rslot * 4) * HS_STRIDE;
        #pragma unroll 4
        for (int jp = jp0; jp < jp0 + 128; jp++) {
            ulonglong2 wA = *(const ulonglong2*)(wbase + (size_t)jp * 4096);
            ulonglong2 wB = *(const ulonglong2*)(wbase + (size_t)jp * 4096 + 4);
            ull h0 = *(const ull*)(hp + 0 * HS_STRIDE + jp * 2);
            ull h1 = *(const ull*)(hp + 1 * HS_STRIDE + jp * 2);
            ull h2 = *(const ull*)(hp + 2 * HS_STRIDE + jp * 2);
            ull h3 = *(const ull*)(hp + 3 * HS_STRIDE + jp * 2);
            fma2(acc[0][0], h0, wA.x); fma2(acc[0][1], h0, wA.y);
            fma2(acc[0][2], h0, wB.x); fma2(acc[0][3], h0, wB.y);
            fma2(acc[1][0], h1, wA.x); fma2(acc[1][1], h1, wA.y);
            fma2(acc[1][2], h1, wB.x); fma2(acc[1][3], h1, wB.y);
            fma2(acc[2][0], h2, wA.x); fma2(acc[2][1], h2, wA.y);
            fma2(acc[2][2], h2, wB.x); fma2(acc[2][3], h2, wB.y);
            fma2(acc[3][0], h3, wA.x); fma2(acc[3][1], h3, wA.y);
            fma2(acc[3][2], h3, wB.x); fma2(acc[3][3], h3, wB.y);
        }

        // combine the two K-halves: jhalf=1 writes partials, jhalf=0 adds + epilogue
        if (jhalf == 1) {
            float* rp = red + (rslot * 16 + uidx) * 16;
            #pragma unroll
            for (int i = 0; i < 4; i++)
                #pragma unroll
                for (int g = 0; g < 4; g++) rp[i * 4 + g] = sum2(acc[i][g]);
        }
        __syncthreads();

        if (jhalf == 0) {
            const float* rp = red + (rslot * 16 + uidx) * 16;
            #pragma unroll
            for (int i = 0; i < 4; i++) {
                int r = r0 + i;
                float iv = sum2(acc[i][0]) + rp[i * 4 + 0] + gin[i].x;
                float fv = sum2(acc[i][1]) + rp[i * 4 + 1] + gin[i].y;
                float gv = sum2(acc[i][2]) + rp[i * 4 + 2] + gin[i].z;
                float ov = sum2(acc[i][3]) + rp[i * 4 + 3] + gin[i].w;
                float ig = sigf(iv), fg = sigf(fv), og = sigf(ov);
                float gg = tanhf(gv);
                c[i] = fg * c[i] + ig * gg;
                float h = og * tanhf(c[i]);
                __stcg(&hout[(size_t)r * Hn + unit], h);
                if (t + 1 == mylen[i]) g_hfin[(size_t)r * Hn + unit] = h;
            }
        }

        // device-wide barrier (128 co-resident blocks; monotonic counter)
        __syncthreads();
        if (tid == 0) {
            __threadfence();
            int old = atomicAdd(&g_ctr, 1);
            if (old == (t + 1) * 128 - 1) {
                g_rel = t + 1;
            } else {
                while (g_rel < t + 1) { }
            }
        }
        __syncthreads();
    }
}

// ---------------- output head ----------------
__global__ void k_out(const float* __restrict__ Wo, const float* __restrict__ bo,
                      float* __restrict__ out) {
    __shared__ float red[14][129];
    int b = blockIdx.x, tid = threadIdx.x;   // 128 threads
    float acc[14];
    #pragma unroll
    for (int o = 0; o < 14; o++) acc[o] = 0.0f;
    for (int q = tid; q < 1024; q += 128) {
        float hv = g_hfin[b * 1024 + q];
        #pragma unroll
        for (int o = 0; o < 14; o++) acc[o] += hv * Wo[o * 1024 + q];
    }
    #pragma unroll
    for (int o = 0; o < 14; o++) red[o][tid] = acc[o];
    __syncthreads();
    if (tid < 14) {
        float s = bo[tid];
        for (int k = 0; k < 128; k++) s += red[tid][k];
        out[b * 14 + tid] = sigf(s);
    }
}

// ---------------- launch ----------------
extern "C" void kernel_launch(void* const* d_in, const int* in_sizes, int n_in,
                              void* d_out, int out_size) {
    const float* x    = (const float*)d_in[0];
    const int*   len  = (const int*)  d_in[1];
    const float* h0   = (const float*)d_in[2];
    const float* c0   = (const float*)d_in[3];
    const float* Wis0 = (const float*)d_in[4];
    const float* bis0 = (const float*)d_in[5];
    const float* Wis1 = (const float*)d_in[6];
    const float* bis1 = (const float*)d_in[7];
    const float* Wih  = (const float*)d_in[8];
    const float* Whh  = (const float*)d_in[9];
    const float* bih  = (const float*)d_in[10];
    const float* bhh  = (const float*)d_in[11];
    const float* Wo   = (const float*)d_in[12];
    const float* bo   = (const float*)d_in[13];
    float* out = (float*)d_out;

    cudaFuncSetAttribute(k_rnn, cudaFuncAttributeMaxDynamicSharedMemorySize, RNN_SMEM);

    k_fold <<<128, 256>>>(Wih, Wis0, bis0, Wis1, bis1, bih, bhh);
    k_wtT  <<<8192, 256>>>(Wih);
    k_whh2 <<<4096, 256>>>(Whh);
    k_inith<<<256, 256>>>(h0);
    k_temb <<<8192, 256>>>(x);
    k_gemm <<<dim3(32, 64), 256>>>(x);
    k_rnn  <<<dim3(32, 4), 256, RNN_SMEM>>>(len, c0);
    k_out  <<<64, 128>>>(Wo, bo, out);
}

// round 11
// speedup vs baseline: 1.6151x; 1.0740x over previous
#include <cuda_runtime.h>

#define Hn   512
#define Tn   128
#define Bn   64
#define NROW 128
#define G4   2048
#define KE   1024
#define NTOK 8192

typedef unsigned long long ull;

// ---------------- static device scratch ----------------
__device__ __align__(16) float g_temb[(size_t)NTOK * KE];      // [tok][1024]
__device__ __align__(16) float g_WtT [(size_t)KE * G4];        // [j][p] p interleaved u*4+g
__device__ __align__(16) float g_Whh2[(size_t)Hn * G4];        // [jp][u*8 + g*2 + par]
__device__ __align__(16) float g_G   [(size_t)Tn * NROW * G4]; // [t'][orig_r][p]
__device__ __align__(16) float g_Msp [2][8][G4];
__device__ __align__(16) float g_cst [2][G4];
__device__ __align__(16) float g_h   [2][NROW * Hn];           // sorted row order
__device__ __align__(16) float g_hfin[NROW * Hn];              // sorted row order
__device__ int g_sortidx[Bn];   // sorted pos -> orig batch (desc by length)
__device__ int g_inv[Bn];       // orig batch -> sorted pos
__device__ int g_maxlen;
__device__ int          g_ctr;
__device__ volatile int g_rel;

// ---------------- helpers ----------------
__device__ __forceinline__ void fma2(ull& d, ull a, ull b) {
    asm("fma.rn.f32x2 %0, %1, %2, %0;" : "+l"(d) : "l"(a), "l"(b));
}
__device__ __forceinline__ float sum2(ull v) {
    float a, b;
    asm("mov.b64 {%0,%1}, %2;" : "=f"(a), "=f"(b) : "l"(v));
    return a + b;
}
__device__ __forceinline__ float sigf(float v) {
    return __fdividef(1.0f, 1.0f + __expf(-v));
}
__device__ __forceinline__ float tanhfast(float v) {
    float e = __expf(2.0f * v);
    return 1.0f - __fdividef(2.0f, e + 1.0f);
}

// ---------------- timestep embeddings ----------------
__global__ void k_temb(const float* __restrict__ x) {
    int tok = blockIdx.x;
    int k   = threadIdx.x;   // 256
    float t0 = x[tok * 16 + 0], t1 = x[tok * 16 + 1];
    float fr = __expf(-9.210340371976184f * (float)k * (1.0f / 256.0f));
    float s0, c0v, s1, c1v;
    __sincosf(t0 * fr, &s0, &c0v);
    __sincosf(t1 * fr, &s1, &c1v);
    float* o = g_temb + (size_t)tok * KE;
    o[k]       = c0v;
    o[k + 256] = s0;
    o[k + 512] = c1v;
    o[k + 768] = s1;
}

// ---------------- prep: permuted W_ih copy ----------------
__global__ void k_wtT(const float* __restrict__ Wih) {
    int i = blockIdx.x * blockDim.x + threadIdx.x;     // 2097152 exact
    int j = i >> 11, p = i & 2047;
    int u = p >> 2, g = p & 3;
    g_WtT[i] = Wih[(size_t)(g * Hn + u) * 1536 + 512 + j];
}

// ---------------- prep: fold segment linears through W_ih ----------------
__global__ void k_fold(const float* __restrict__ Wih,
                       const float* __restrict__ Wis0, const float* __restrict__ bis0,
                       const float* __restrict__ Wis1, const float* __restrict__ bis1,
                       const float* __restrict__ bih,  const float* __restrict__ bhh) {
    int idx = blockIdx.x * blockDim.x + threadIdx.x;   // 32768 = 2048 p * 16 items
    int p = idx >> 4, item = idx & 15;
    int u = p >> 2, g = p & 3;
    const float* wr = Wih + (size_t)(g * Hn + u) * 1536;
    float acc = 0.0f;
    if (item < 8) {
        for (int k = 0; k < Hn; k++) acc += wr[k] * Wis0[k * 8 + item];
        g_Msp[0][item][p] = acc;
    } else if (item < 14) {
        int m = item - 8;
        for (int k = 0; k < Hn; k++) acc += wr[k] * Wis1[k * 6 + m];
        g_Msp[1][m][p] = acc;
    } else if (item == 14) {
        for (int k = 0; k < Hn; k++) acc += wr[k] * bis0[k];
        g_cst[0][p] = acc + bih[g * Hn + u] + bhh[g * Hn + u];
    } else {
        for (int k = 0; k < Hn; k++) acc += wr[k] * bis1[k];
        g_cst[1][p] = acc + bih[g * Hn + u] + bhh[g * Hn + u];
    }
}

// ---------------- big GEMM: temb -> gate pre-activations (+ seg fold epilogue) ----------------
__global__ void __launch_bounds__(256) k_gemm(const float* __restrict__ x,
                                              const int* __restrict__ lengths) {
    __shared__ float As[16 * 128 * 2];   // [kp][m][par]
    __shared__ float Bs[16 * 64 * 2];    // [kp][n][par]
    int b  = blockIdx.y;
    int pt = blockIdx.x * 64;
    int tid = threadIdx.x;
    int tx = tid & 15, ty = tid >> 4;
    int m0 = ty * 8, n0 = tx * 4;
    int blen = __ldg(&lengths[b]);

    ull acc[8][4];
    #pragma unroll
    for (int i = 0; i < 8; i++)
        #pragma unroll
        for (int j = 0; j < 4; j++) acc[i][j] = 0ull;

    const float* Abase = g_temb + (size_t)b * 128 * KE;

    for (int k0 = 0; k0 < KE; k0 += 32) {
        #pragma unroll
        for (int it = 0; it < 4; it++) {
            int m  = (tid >> 3) + it * 32;
            int kk = (tid & 7) * 4;
            float4 v = *(const float4*)(Abase + (size_t)m * KE + k0 + kk);
            int kp = kk >> 1;
            As[(kp * 128 + m) * 2 + 0]       = v.x;
            As[(kp * 128 + m) * 2 + 1]       = v.y;
            As[((kp + 1) * 128 + m) * 2 + 0] = v.z;
            As[((kp + 1) * 128 + m) * 2 + 1] = v.w;
        }
        #pragma unroll
        for (int it = 0; it < 2; it++) {
            int j  = (tid >> 4) + it * 16;
            int pp = (tid & 15) * 4;
            float4 v = *(const float4*)(g_WtT + (size_t)(k0 + j) * G4 + pt + pp);
            int kp = j >> 1, par = j & 1;
            Bs[(kp * 64 + pp + 0) * 2 + par] = v.x;
            Bs[(kp * 64 + pp + 1) * 2 + par] = v.y;
            Bs[(kp * 64 + pp + 2) * 2 + par] = v.z;
            Bs[(kp * 64 + pp + 3) * 2 + par] = v.w;
        }
        __syncthreads();
        #pragma unroll
        for (int kp = 0; kp < 16; kp++) {
            ull a2[8], b2[4];
            #pragma unroll
            for (int i = 0; i < 8; i += 2) {
                ulonglong2 t = *(const ulonglong2*)&As[(kp * 128 + m0 + i) * 2];
                a2[i] = t.x; a2[i + 1] = t.y;
            }
            #pragma unroll
            for (int i = 0; i < 4; i += 2) {
                ulonglong2 t = *(const ulonglong2*)&Bs[(kp * 64 + n0 + i) * 2];
                b2[i] = t.x; b2[i + 1] = t.y;
            }
            #pragma unroll
            for (int i = 0; i < 8; i++)
                #pragma unroll
                for (int j = 0; j < 4; j++) fma2(acc[i][j], a2[i], b2[j]);
        }
        __syncthreads();
    }

    #pragma unroll
    for (int i = 0; i < 8; i++) {
        int t = m0 + i;
        const float* xr = x + ((size_t)b * 128 + t) * 16;
        float cval[4];
        #pragma unroll
        for (int j = 0; j < 4; j++) cval[j] = sum2(acc[i][j]);
        #pragma unroll
        for (int se = 0; se < 2; se++) {
            int L = t * 2 + se;
            int sp = L >> 7, tp = L & 127;
            if (tp >= blen) continue;          // never read by the recurrence
            float4 outv;
            float* ov = &outv.x;
            int p = pt + n0;
            #pragma unroll
            for (int j = 0; j < 4; j++) {
                float v = cval[j] + g_cst[se][p + j];
                if (se == 0) {
                    #pragma unroll
                    for (int m = 0; m < 8; m++) v += xr[2 + m] * g_Msp[0][m][p + j];
                } else {
                    #pragma unroll
                    for (int m = 0; m < 6; m++) v += xr[10 + m] * g_Msp[1][m][p + j];
                }
                ov[j] = v;
            }
            *(float4*)&g_G[((size_t)tp * NROW + (b * 2 + sp)) * G4 + p] = outv;
        }
    }
}

// ---------------- sort batches by length (desc), single thread ----------------
__global__ void k_sort(const int* __restrict__ lengths) {
    if (threadIdx.x == 0 && blockIdx.x == 0) {
        int idx[Bn], len[Bn];
        for (int i = 0; i < Bn; i++) { idx[i] = i; len[i] = lengths[i]; }
        for (int a = 0; a < Bn - 1; a++) {
            int m = a;
            for (int b2 = a + 1; b2 < Bn; b2++) if (len[b2] > len[m]) m = b2;
            int tl = len[a]; len[a] = len[m]; len[m] = tl;
            int ti = idx[a]; idx[a] = idx[m]; idx[m] = ti;
        }
        for (int i = 0; i < Bn; i++) { g_sortidx[i] = idx[i]; g_inv[idx[i]] = i; }
        g_maxlen = len[0];
    }
}

// ---------------- prep: permuted W_hh copy ----------------
__global__ void k_whh2(const float* __restrict__ Whh) {
    int i = blockIdx.x * blockDim.x + threadIdx.x;     // 1048576 exact
    int jp = i >> 12, rem = i & 4095;
    int u = rem >> 3, g = (rem >> 1) & 3, par = i & 1;
    g_Whh2[i] = Whh[(size_t)(g * Hn + u) * Hn + 2 * jp + par];
}

// ---------------- init h (sorted row order) + barrier reset ----------------
__global__ void k_inith(const float* __restrict__ h0) {
    int i = blockIdx.x * blockDim.x + threadIdx.x;     // 65536 exact
    int rs = i >> 9, u = i & 511;
    g_h[0][i] = h0[g_sortidx[rs >> 1] * Hn + u];
    if (i == 0) { g_ctr = 0; g_rel = 0; }
}

// ---------------- persistent recurrence kernel ----------------
// grid (32 unit-tiles, 4 row-groups) = 128 co-resident blocks, 256 threads.
// Rows are length-sorted desc; a row-group skips compute once all its rows are done.
#define HS_STRIDE 516
#define RED_OFF   (32 * HS_STRIDE)
#define RNN_SMEM  ((RED_OFF + 128 * 16) * 4)

__global__ void __launch_bounds__(256, 1) k_rnn(const int* __restrict__ lengths,
                                                const float* __restrict__ c0) {
    extern __shared__ float hs[];            // [32 rows][516] + red[128][16]
    float* red = hs + RED_OFF;
    int tid    = threadIdx.x;
    int uidx   = tid & 15;
    int rslot  = (tid >> 4) & 7;             // 0..7
    int jhalf  = tid >> 7;                   // 0/1
    int unit   = blockIdx.x * 16 + uidx;
    int rowbase = blockIdx.y * 32;
    int r0 = rowbase + rslot * 4;            // sorted row
    int jp0 = jhalf * 128;

    float c[4];
    int   mylen[4];
    const float* gbase[4];
    #pragma unroll
    for (int i = 0; i < 4; i++) {
        int sr = r0 + i;
        int ob = g_sortidx[sr >> 1];                       // original batch
        c[i]     = __ldg(&c0[ob * Hn + unit]);
        mylen[i] = __ldg(&lengths[ob]);
        gbase[i] = g_G + (size_t)(ob * 2 + (sr & 1)) * G4 + unit * 4;
    }
    int groupmax = __ldg(&lengths[g_sortidx[rowbase >> 1]]);  // first = largest in group
    int tmax = g_maxlen;

    const float* wbase = g_Whh2 + unit * 8;

    for (int t = 0; t < tmax; t++) {
        if (t < groupmax) {
            const float* hin  = g_h[t & 1];
            float*       hout = g_h[(t + 1) & 1];

            // stage 32-row h tile (4096 float4s); bypass L1
            #pragma unroll
            for (int e = tid; e < 4096; e += 256) {
                int rl = e >> 7, u4 = (e & 127) << 2;
                float4 v = __ldcg((const float4*)(hin + (size_t)(rowbase + rl) * Hn + u4));
                *(float4*)&hs[rl * HS_STRIDE + u4] = v;
            }
            __syncthreads();

            float4 gin[4];
            if (jhalf == 0) {
                #pragma unroll
                for (int i = 0; i < 4; i++)
                    gin[i] = __ldcg((const float4*)(gbase[i] + (size_t)t * NROW * G4));
            }

            ull acc[4][4];
            #pragma unroll
            for (int i = 0; i < 4; i++)
                #pragma unroll
                for (int g = 0; g < 4; g++) acc[i][g] = 0ull;

            const float* hp = hs + (size_t)(rslot * 4) * HS_STRIDE;
            #pragma unroll 4
            for (int jp = jp0; jp < jp0 + 128; jp++) {
                ulonglong2 wA = *(const ulonglong2*)(wbase + (size_t)jp * 4096);
                ulonglong2 wB = *(const ulonglong2*)(wbase + (size_t)jp * 4096 + 4);
                ull h0 = *(const ull*)(hp + 0 * HS_STRIDE + jp * 2);
                ull h1 = *(const ull*)(hp + 1 * HS_STRIDE + jp * 2);
                ull h2 = *(const ull*)(hp + 2 * HS_STRIDE + jp * 2);
                ull h3 = *(const ull*)(hp + 3 * HS_STRIDE + jp * 2);
                fma2(acc[0][0], h0, wA.x); fma2(acc[0][1], h0, wA.y);
                fma2(acc[0][2], h0, wB.x); fma2(acc[0][3], h0, wB.y);
                fma2(acc[1][0], h1, wA.x); fma2(acc[1][1], h1, wA.y);
                fma2(acc[1][2], h1, wB.x); fma2(acc[1][3], h1, wB.y);
                fma2(acc[2][0], h2, wA.x); fma2(acc[2][1], h2, wA.y);
                fma2(acc[2][2], h2, wB.x); fma2(acc[2][3], h2, wB.y);
                fma2(acc[3][0], h3, wA.x); fma2(acc[3][1], h3, wA.y);
                fma2(acc[3][2], h3, wB.x); fma2(acc[3][3], h3, wB.y);
            }

            if (jhalf == 1) {
                float* rp = red + (rslot * 16 + uidx) * 16;
                #pragma unroll
                for (int i = 0; i < 4; i++)
                    #pragma unroll
                    for (int g = 0; g < 4; g++) rp[i * 4 + g] = sum2(acc[i][g]);
            }
            __syncthreads();

            if (jhalf == 0) {
                const float* rp = red + (rslot * 16 + uidx) * 16;
                #pragma unroll
                for (int i = 0; i < 4; i++) {
                    int r = r0 + i;
                    float iv = sum2(acc[i][0]) + rp[i * 4 + 0] + gin[i].x;
                    float fv = sum2(acc[i][1]) + rp[i * 4 + 1] + gin[i].y;
                    float gv = sum2(acc[i][2]) + rp[i * 4 + 2] + gin[i].z;
                    float ov = sum2(acc[i][3]) + rp[i * 4 + 3] + gin[i].w;
                    float ig = sigf(iv), fg = sigf(fv), og = sigf(ov);
                    float gg = tanhfast(gv);
                    c[i] = fg * c[i] + ig * gg;
                    float h = og * tanhfast(c[i]);
                    __stcg(&hout[(size_t)r * Hn + unit], h);
                    if (t + 1 == mylen[i]) g_hfin[(size_t)r * Hn + unit] = h;
                }
            }
            __syncthreads();
        }

        // device-wide barrier (128 co-resident blocks; monotonic counter)
        if (tid == 0) {
            __threadfence();
            int old = atomicAdd(&g_ctr, 1);
            if (old == (t + 1) * 128 - 1) {
                g_rel = t + 1;
            } else {
                while (g_rel < t + 1) { }
            }
        }
        __syncthreads();
    }
}

// ---------------- output head ----------------
__global__ void k_out(const float* __restrict__ Wo, const float* __restrict__ bo,
                      float* __restrict__ out) {
    __shared__ float red[14][129];
    int b = blockIdx.x, tid = threadIdx.x;   // 128 threads
    int pos = g_inv[b];
    float acc[14];
    #pragma unroll
    for (int o = 0; o < 14; o++) acc[o] = 0.0f;
    for (int q = tid; q < 1024; q += 128) {
        int row = pos * 2 + (q >> 9);
        float hv = g_hfin[row * Hn + (q & 511)];
        #pragma unroll
        for (int o = 0; o < 14; o++) acc[o] += hv * Wo[o * 1024 + q];
    }
    #pragma unroll
    for (int o = 0; o < 14; o++) red[o][tid] = acc[o];
    __syncthreads();
    if (tid < 14) {
        float s = bo[tid];
        for (int k = 0; k < 128; k++) s += red[tid][k];
        out[b * 14 + tid] = sigf(s);
    }
}

// ---------------- launch ----------------
extern "C" void kernel_launch(void* const* d_in, const int* in_sizes, int n_in,
                              void* d_out, int out_size) {
    const float* x    = (const float*)d_in[0];
    const int*   len  = (const int*)  d_in[1];
    const float* h0   = (const float*)d_in[2];
    const float* c0   = (const float*)d_in[3];
    const float* Wis0 = (const float*)d_in[4];
    const float* bis0 = (const float*)d_in[5];
    const float* Wis1 = (const float*)d_in[6];
    const float* bis1 = (const float*)d_in[7];
    const float* Wih  = (const float*)d_in[8];
    const float* Whh  = (const float*)d_in[9];
    const float* bih  = (const float*)d_in[10];
    const float* bhh  = (const float*)d_in[11];
    const float* Wo   = (const float*)d_in[12];
    const float* bo   = (const float*)d_in[13];
    float* out = (float*)d_out;

    cudaFuncSetAttribute(k_rnn, cudaFuncAttributeMaxDynamicSharedMemorySize, RNN_SMEM);

    k_temb <<<8192, 256>>>(x);                                   // 1
    k_wtT  <<<8192, 256>>>(Wih);                                 // 2
    k_fold <<<128, 256>>>(Wih, Wis0, bis0, Wis1, bis1, bih, bhh);// 3
    k_gemm <<<dim3(32, 64), 256>>>(x, len);                      // 4  <- profiled slot
    k_sort <<<1, 32>>>(len);                                     // 5
    k_whh2 <<<4096, 256>>>(Whh);                                 // 6
    k_inith<<<256, 256>>>(h0);                                   // 7
    k_rnn  <<<dim3(32, 4), 256, RNN_SMEM>>>(len, c0);            // 8
    k_out  <<<64, 128>>>(Wo, bo, out);                           // 9
}